// round 2
// baseline (speedup 1.0000x reference)
#include <cuda_runtime.h>
#include <math.h>

#define N_TOT    87296
#define SEL_TOT  4256
#define SEL_PAD  4352
#define SEL_PAD2 4352
#define WW       136
#define JTILES   34
#define EQCAP    2048

// ---------------- scratch (device globals; zero-initialized) ---------------
__device__ float    g_key[N_TOT];
__device__ int      g_cls[N_TOT];
__device__ float    g_selKey[SEL_TOT];
__device__ int      g_selCls[SEL_TOT];
__device__ int      g_selTie[SEL_TOT];
__device__ float4   g_selBox[SEL_TOT];
__device__ float    g_srtScore[SEL_PAD];
__device__ int      g_srtCls[SEL_PAD];
__device__ int      g_srtValid[SEL_PAD];
__device__ float4   g_srtBox[SEL_PAD];
__device__ unsigned g_Mt[(size_t)WW * SEL_PAD2];   // column-major: Mt[w][j]
__device__ unsigned g_keep[2][WW];
__device__ unsigned g_changeArr[16];

__device__ __forceinline__ unsigned fflip(float f) {
    unsigned u = __float_as_uint(f);
    return (u & 0x80000000u) ? ~u : (u | 0x80000000u);
}

// ---------------- 1. per-anchor class max (warp per anchor) ----------------
__global__ void scoreKernel(const float* __restrict__ c0, const float* __restrict__ c1,
                            const float* __restrict__ c2, const float* __restrict__ c3,
                            const float* __restrict__ c4) {
    int warp = (blockIdx.x * blockDim.x + threadIdx.x) >> 5;
    int lane = threadIdx.x & 31;
    if (warp >= N_TOT) return;
    int off;
    const float* base;
    if      (warp < 65536) { off = 0;     base = c0; }
    else if (warp < 81920) { off = 65536; base = c1; }
    else if (warp < 86016) { off = 81920; base = c2; }
    else if (warp < 87040) { off = 86016; base = c3; }
    else                   { off = 87040; base = c4; }
    int a = warp - off;
    const float* p = base + (size_t)a * 80;
    float v = -1e30f; int bi = 0;
    for (int c = lane; c < 80; c += 32) {
        float x = p[c];
        if (x > v) { v = x; bi = c; }
    }
    for (int o = 16; o; o >>= 1) {
        float ov = __shfl_down_sync(0xffffffffu, v, o);
        int   oi = __shfl_down_sync(0xffffffffu, bi, o);
        if (ov > v || (ov == v && oi < bi)) { v = ov; bi = oi; }
    }
    if (lane == 0) {
        float ps = 1.0f / (1.0f + expf(-v));
        g_key[warp] = (ps > 0.05f) ? ps : -1.0f;
        g_cls[warp] = bi + 1;
    }
}

// ---------------- 2. per-level exact radix-select top-k + clip -------------
__global__ void selectKernel(const float* __restrict__ r0, const float* __restrict__ r1,
                             const float* __restrict__ r2, const float* __restrict__ r3,
                             const float* __restrict__ r4, const float* __restrict__ loc) {
    const int LNv[5]  = {65536, 16384, 4096, 1024, 256};
    const int OFFv[5] = {0, 65536, 81920, 86016, 87040};
    const int SOFF[5] = {0, 1000, 2000, 3000, 4000};
    const int LKv[5]  = {1000, 1000, 1000, 1000, 256};
    int lvl = blockIdx.x;
    int n = LNv[lvl], off = OFFv[lvl], k = LKv[lvl], sbase = SOFF[lvl];
    const float* key = g_key + off;
    const float* reg = (lvl == 0) ? r0 : (lvl == 1) ? r1 : (lvl == 2) ? r2 : (lvl == 3) ? r3 : r4;

    __shared__ unsigned hist[4][256];
    __shared__ unsigned sCur, sNeed;
    __shared__ int      eqBuf[EQCAP];
    __shared__ int      eqSel[EQCAP];
    int tid = threadIdx.x;
    int hgrp = (tid >> 5) & 3;
    if (tid == 0) { sCur = 0u; sNeed = (unsigned)k; }
    __syncthreads();

    for (int r = 3; r >= 0; r--) {
        for (int i = tid; i < 1024; i += blockDim.x) hist[i >> 8][i & 255] = 0u;
        __syncthreads();
        unsigned cur = sCur;
        unsigned hm  = (r == 3) ? 0u : (0xFFFFFFFFu << ((r + 1) * 8));
        for (int i = tid; i < n; i += blockDim.x) {
            unsigned u = fflip(key[i]);
            if ((u & hm) == cur) atomicAdd(&hist[hgrp][(u >> (r * 8)) & 255u], 1u);
        }
        __syncthreads();
        if (tid == 0) {
            unsigned need = sNeed, acc = 0; int b = 0;
            for (int bb = 255; bb >= 0; bb--) {
                unsigned h = hist[0][bb] + hist[1][bb] + hist[2][bb] + hist[3][bb];
                if (acc + h >= need) { b = bb; break; }
                acc += h;
            }
            sNeed = need - acc;
            sCur  = cur | ((unsigned)b << (r * 8));
        }
        __syncthreads();
    }
    unsigned pivot = sCur;
    int need = (int)sNeed;
    int G = k - need;
    __shared__ int cg, ce;
    if (tid == 0) { cg = 0; ce = 0; }
    __syncthreads();

    float l0 = loc[0], l1 = loc[1], l2 = loc[2], l3 = loc[3];
    for (int i = tid; i < n; i += blockDim.x) {
        float kf = key[i];
        unsigned u = fflip(kf);
        int slot = -1;
        if (u > pivot) slot = sbase + atomicAdd(&cg, 1);
        else if (u == pivot) {
            int t = atomicAdd(&ce, 1);
            if (t < EQCAP) eqBuf[t] = i;
        }
        if (slot >= 0) {
            g_selKey[slot] = kf;
            g_selCls[slot] = g_cls[off + i];
            g_selTie[slot] = (lvl << 17) | i;
            float b0 = reg[(size_t)i * 4 + 0], b1 = reg[(size_t)i * 4 + 1];
            float b2 = reg[(size_t)i * 4 + 2], b3 = reg[(size_t)i * 4 + 3];
            g_selBox[slot] = make_float4(fmaxf(b0, l0), fmaxf(b1, l1),
                                         fminf(b2, l2), fminf(b3, l3));
        }
    }
    __syncthreads();
    // pick the `need` smallest indices among equal-to-pivot (matches top_k ties)
    if (tid == 0) {
        int m = ce; if (m > EQCAP) m = EQCAP;
        // selection sort of first `need` smallest into eqSel (need <= m)
        for (int t = 0; t < need; t++) {
            int best = -1, bestv = 0x7FFFFFFF;
            for (int q = 0; q < m; q++) {
                int v = eqBuf[q];
                if (v >= 0 && v < bestv) { bestv = v; best = q; }
            }
            eqSel[t] = bestv;
            if (best >= 0) eqBuf[best] = -1;
        }
    }
    __syncthreads();
    if (tid < need) {
        int i = eqSel[tid];
        int slot = sbase + G + tid;
        g_selKey[slot] = key[i];
        g_selCls[slot] = g_cls[off + i];
        g_selTie[slot] = (lvl << 17) | i;
        float b0 = reg[(size_t)i * 4 + 0], b1 = reg[(size_t)i * 4 + 1];
        float b2 = reg[(size_t)i * 4 + 2], b3 = reg[(size_t)i * 4 + 3];
        g_selBox[slot] = make_float4(fmaxf(b0, l0), fmaxf(b1, l1),
                                     fminf(b2, l2), fminf(b3, l3));
    }
}

// ---------------- 3. deterministic rank-sort of 4256 elements --------------
__global__ void rankKernel() {
    __shared__ unsigned long long sk[SEL_TOT];
    int tid = threadIdx.x;
    int gt  = blockIdx.x * blockDim.x + tid;
    for (int i = tid; i < SEL_TOT; i += blockDim.x) {
        float kf = g_selKey[i];
        float ss = (kf > 0.0f) ? kf : 0.0f;           // invalid -> 0 (matches reference)
        unsigned tie = (unsigned)g_selTie[i];
        sk[i] = ((unsigned long long)fflip(ss) << 20) |
                (unsigned long long)(0xFFFFFu - tie);  // desc score, asc (level,anchor)
    }
    __syncthreads();
    if (gt < SEL_TOT) {
        unsigned long long mine = sk[gt];
        int rank = 0;
        for (int i = 0; i < SEL_TOT; i++) rank += (sk[i] > mine) ? 1 : 0;
        float kf = g_selKey[gt];
        g_srtScore[rank] = (kf > 0.0f) ? kf : 0.0f;
        g_srtValid[rank] = (kf > 0.0f) ? 1 : 0;
        g_srtCls[rank]   = g_selCls[gt];
        g_srtBox[rank]   = g_selBox[gt];
    }
    if (gt < WW) { g_keep[0][gt] = 0xFFFFFFFFu; }
    if (gt < 16) g_changeArr[gt] = 0u;
}

// ------- 4. suppression bitmask, column-major (bit k of word w, col j) ------
__global__ void matrixKernel() {
    int w = blockIdx.y;                       // keep-word index (k chunk)
    int jbase = blockIdx.x * 128;
    int kbase = w * 32;
    if (kbase >= jbase + 127) return;         // no j in tile has k < j here
    __shared__ float4 kb[32];
    if (threadIdx.x < 32) kb[threadIdx.x] = g_srtBox[kbase + threadIdx.x];
    __syncthreads();
    int j = jbase + threadIdx.x;
    if (j >= SEL_TOT || kbase >= j) return;
    float4 bj = g_srtBox[j];
    float aj = fmaxf(bj.z - bj.x, 0.f) * fmaxf(bj.w - bj.y, 0.f);
    unsigned word = 0u;
    int kmax = j - kbase; if (kmax > 32) kmax = 32;
    #pragma unroll 8
    for (int t = 0; t < kmax; t++) {
        float4 bk = kb[t];
        float ak = fmaxf(bk.z - bk.x, 0.f) * fmaxf(bk.w - bk.y, 0.f);
        float iy1 = fmaxf(bk.x, bj.x), ix1 = fmaxf(bk.y, bj.y);
        float iy2 = fminf(bk.z, bj.z), ix2 = fminf(bk.w, bj.w);
        float inter = fmaxf(iy2 - iy1, 0.f) * fmaxf(ix2 - ix1, 0.f);
        float uni = aj + ak - inter;
        float iou = inter / fmaxf(uni, 1e-9f);
        if (iou > 0.5f) word |= (1u << t);
    }
    g_Mt[(size_t)w * SEL_PAD2 + j] = word;
}

// ------------- 5. one Jacobi keep-iteration (launched 16 times) ------------
__global__ void iterKernel(int it) {
    const unsigned* src = g_keep[it & 1];
    unsigned*       dst = g_keep[(it + 1) & 1];
    if (it > 0 && g_changeArr[it - 1] == 0u) {      // converged: idempotent copy
        if (blockIdx.x == 0)
            for (int w = threadIdx.x; w < WW; w += 128) dst[w] = src[w];
        return;
    }
    __shared__ unsigned sK[WW];
    int tid = threadIdx.x;
    for (int w = tid; w < WW; w += 128) sK[w] = src[w];
    __syncthreads();
    int j = blockIdx.x * 128 + tid;
    int wmax = (j > 0 && j < SEL_TOT) ? ((j - 1) >> 5) : -1;
    unsigned acc = 0u;
    const unsigned* col = g_Mt + j;
    for (int w = 0; w <= wmax; w++) acc |= col[(size_t)w * SEL_PAD2] & sK[w];
    bool keepNew = (acc == 0u);
    unsigned bal = __ballot_sync(0xffffffffu, keepNew);
    if ((tid & 31) == 0) dst[j >> 5] = bal;
    bool changed = keepNew != (((sK[j >> 5] >> (j & 31)) & 1u) != 0u);
    if (__any_sync(0xffffffffu, changed) && (tid & 31) == 0) g_changeArr[it] = 1u;
}

// ---------------- 6. final top-100 + rescale + write -----------------------
__global__ void finalKernel(float* __restrict__ out, const float* __restrict__ loc,
                            int out_size) {
    __shared__ unsigned char kept[SEL_TOT];
    __shared__ int sel[100];
    int tid = threadIdx.x;
    for (int j = tid; j < SEL_TOT; j += blockDim.x) {
        unsigned w = g_keep[0][j >> 5];             // after 16 iters, parity back to 0
        kept[j] = (unsigned char)(((w >> (j & 31)) & 1u) && g_srtValid[j]);
    }
    __syncthreads();
    if (tid == 0) {
        int cnt = 0;
        for (int j = 0; j < SEL_TOT && cnt < 100; j++) if (kept[j])  sel[cnt++] = j;
        for (int j = 0; j < SEL_TOT && cnt < 100; j++) if (!kept[j]) sel[cnt++] = j;
    }
    __syncthreads();
    if (tid < 100) {
        int j = sel[tid];
        float vy1 = loc[0], vx1 = loc[1], vy2 = loc[2], vx2 = loc[3];
        float oh = loc[4], ow = loc[5];
        float sy = oh / fmaxf(vy2 - vy1, 1e-6f);
        float sx = ow / fmaxf(vx2 - vx1, 1e-6f);
        float4 b = g_srtBox[j];
        if (tid * 4 + 3 < out_size) {
            out[tid * 4 + 0] = (b.x - vy1) * sy;
            out[tid * 4 + 1] = (b.y - vx1) * sx;
            out[tid * 4 + 2] = (b.z - vy1) * sy;
            out[tid * 4 + 3] = (b.w - vx1) * sx;
        }
        if (400 + tid < out_size) out[400 + tid] = (float)g_srtCls[j];
        if (500 + tid < out_size) out[500 + tid] = kept[j] ? g_srtScore[j] : 0.0f;
    }
}

// ---------------- host launcher --------------------------------------------
extern "C" void kernel_launch(void* const* d_in, const int* in_sizes, int n_in,
                              void* d_out, int out_size) {
    const float *cls[5] = {0, 0, 0, 0, 0};
    const float *reg[5] = {0, 0, 0, 0, 0};
    const float *loc = 0;
    for (int i = 0; i < n_in; i++) {
        switch (in_sizes[i]) {
            case 5242880: cls[0] = (const float*)d_in[i]; break;
            case 1310720: cls[1] = (const float*)d_in[i]; break;
            case 327680:  cls[2] = (const float*)d_in[i]; break;
            case 81920:   cls[3] = (const float*)d_in[i]; break;
            case 20480:   cls[4] = (const float*)d_in[i]; break;
            case 262144:  reg[0] = (const float*)d_in[i]; break;
            case 65536:   reg[1] = (const float*)d_in[i]; break;
            case 16384:   reg[2] = (const float*)d_in[i]; break;
            case 4096:    reg[3] = (const float*)d_in[i]; break;
            case 1024:    reg[4] = (const float*)d_in[i]; break;
            case 6:       loc    = (const float*)d_in[i]; break;
            default: break;
        }
    }
    int blocks = (N_TOT * 32 + 255) / 256;
    scoreKernel<<<blocks, 256>>>(cls[0], cls[1], cls[2], cls[3], cls[4]);
    selectKernel<<<5, 1024>>>(reg[0], reg[1], reg[2], reg[3], reg[4], loc);
    rankKernel<<<JTILES, 128>>>();
    dim3 mg(JTILES, WW);
    matrixKernel<<<mg, 128>>>();
    for (int it = 0; it < 16; it++) iterKernel<<<JTILES, 128>>>(it);
    finalKernel<<<1, 128>>>((float*)d_out, loc, out_size);
}